// round 3
// baseline (speedup 1.0000x reference)
#include <cuda_runtime.h>
#include <cuda_bf16.h>

#define NN   50000
#define NE   800000
#define FIN  128
#define FOUT 64
#define SLOPE 0.2f

// ---------------- scratch (__device__ globals; no allocations allowed) -----
__device__ float g_h[(size_t)NN * FOUT];   // x @ W
__device__ float g_asrc[NN];               // h . att_src
__device__ float g_adst[NN];               // h . att_dst
__device__ int   g_cnt[NN];                // in-degree (excl self loop)
__device__ int   g_start[NN];              // CSR offsets
__device__ int   g_cursor[NN];             // scatter cursors
__device__ int   g_src[NE];                // CSR: src node per edge (dst-sorted)

__device__ __forceinline__ float leaky(float v) { return v > 0.f ? v : SLOPE * v; }

// packed f32x2 helpers (FFMA2 is PTX-only; ptxas never auto-fuses)
__device__ __forceinline__ long long pk2(float lo, float hi) {
    long long r;
    asm("mov.b64 %0, {%1,%2};" : "=l"(r) : "f"(lo), "f"(hi));
    return r;
}
__device__ __forceinline__ void unpk2(long long v, float& lo, float& hi) {
    asm("mov.b64 {%0,%1}, %2;" : "=f"(lo), "=f"(hi) : "l"(v));
}
__device__ __forceinline__ long long ffma2(long long a, long long b, long long c) {
    long long d;
    asm("fma.rn.f32x2 %0, %1, %2, %3;" : "=l"(d) : "l"(a), "l"(b), "l"(c));
    return d;
}

// ---------------------------------------------------------------------------
// K0: zero degree counters
// ---------------------------------------------------------------------------
__global__ __launch_bounds__(256) void k_init()
{
    int i = blockIdx.x * blockDim.x + threadIdx.x;
    if (i < NN) g_cnt[i] = 0;
}

// ---------------------------------------------------------------------------
// K1: dst histogram (RED, no return)
// ---------------------------------------------------------------------------
__global__ __launch_bounds__(256) void k_count(const int* __restrict__ ei)
{
    int i = blockIdx.x * blockDim.x + threadIdx.x;
    if (i < NE) atomicAdd(&g_cnt[ei[NE + i]], 1);
}

// ---------------------------------------------------------------------------
// K2: h = x @ W with packed f32x2 FMAs; 4 rows/warp, W+x reuse from shared.
//     Epilogue: a_src[row], a_dst[row].
// ---------------------------------------------------------------------------
#define GEMM_ROWS 16          // rows per block (4 warps x 4 rows)
__global__ __launch_bounds__(128) void k_gemm(
    const float* __restrict__ x, const float* __restrict__ W,
    const float* __restrict__ att_src, const float* __restrict__ att_dst)
{
    __shared__ long long Wsh[FIN * 32];        // 32 KB: Wsh[k*32+l]=(W[k][2l],W[k][2l+1])
    __shared__ long long Xd[GEMM_ROWS * FIN];  // 16 KB: x duplicated (v,v) per lane

    int tid = threadIdx.x;
    int row0 = blockIdx.x * GEMM_ROWS;

    const float2* W2 = (const float2*)W;
    for (int idx = tid; idx < FIN * 32; idx += 128) {
        float2 wv = W2[idx];
        Wsh[idx] = pk2(wv.x, wv.y);
    }
    for (int idx = tid; idx < GEMM_ROWS * 32; idx += 128) {
        int r = idx >> 5, c = idx & 31;
        int row = row0 + r;
        float4 v = (row < NN) ? ((const float4*)(x + (size_t)row * FIN))[c]
                              : make_float4(0.f, 0.f, 0.f, 0.f);
        long long* dst = &Xd[r * FIN + c * 4];
        dst[0] = pk2(v.x, v.x); dst[1] = pk2(v.y, v.y);
        dst[2] = pk2(v.z, v.z); dst[3] = pk2(v.w, v.w);
    }
    __syncthreads();

    int lane = tid & 31, w = tid >> 5;
    float2 as2 = ((const float2*)att_src)[lane];
    float2 ad2 = ((const float2*)att_dst)[lane];

    long long acc[4] = {0, 0, 0, 0};
    #pragma unroll 4
    for (int k = 0; k < FIN; k += 2) {
        long long w0 = Wsh[k * 32 + lane];
        long long w1 = Wsh[(k + 1) * 32 + lane];
        #pragma unroll
        for (int r = 0; r < 4; r++) {
            longlong2 xx = *(const longlong2*)&Xd[(w * 4 + r) * FIN + k];
            acc[r] = ffma2(xx.x, w0, acc[r]);
            acc[r] = ffma2(xx.y, w1, acc[r]);
        }
    }

    #pragma unroll
    for (int r = 0; r < 4; r++) {
        int row = row0 + w * 4 + r;
        if (row >= NN) continue;
        float a0, a1; unpk2(acc[r], a0, a1);
        ((float2*)(g_h + (size_t)row * FOUT))[lane] = make_float2(a0, a1);
        float ps = a0 * as2.x + a1 * as2.y;
        float pd = a0 * ad2.x + a1 * ad2.y;
        #pragma unroll
        for (int off = 16; off; off >>= 1) {
            ps += __shfl_xor_sync(0xffffffffu, ps, off);
            pd += __shfl_xor_sync(0xffffffffu, pd, off);
        }
        if (lane == 0) { g_asrc[row] = ps; g_adst[row] = pd; }
    }
}

// ---------------------------------------------------------------------------
// K3: single-block exclusive scan of degrees -> g_start, g_cursor
// ---------------------------------------------------------------------------
__global__ __launch_bounds__(1024) void k_scan()
{
    __shared__ int bs[1024];
    const int CH = (NN + 1023) / 1024;   // 49
    int t = threadIdx.x;
    int base = t * CH;
    int s = 0;
    for (int i = 0; i < CH; i++) {
        int idx = base + i;
        if (idx < NN) s += g_cnt[idx];
    }
    bs[t] = s;
    __syncthreads();
    for (int off = 1; off < 1024; off <<= 1) {
        int v = (t >= off) ? bs[t - off] : 0;
        __syncthreads();
        bs[t] += v;
        __syncthreads();
    }
    int run = (t == 0) ? 0 : bs[t - 1];
    for (int i = 0; i < CH; i++) {
        int idx = base + i;
        if (idx < NN) {
            g_start[idx] = run;
            g_cursor[idx] = run;
            run += g_cnt[idx];
        }
    }
}

// ---------------------------------------------------------------------------
// K4: scatter edges into dst-sorted CSR (src only; logits computed in K5)
// ---------------------------------------------------------------------------
__global__ __launch_bounds__(256) void k_scatter(const int* __restrict__ ei)
{
    int i = blockIdx.x * blockDim.x + threadIdx.x;
    if (i >= NE) return;
    int d = ei[NE + i];
    int pos = atomicAdd(&g_cursor[d], 1);
    g_src[pos] = ei[i];
}

// ---------------------------------------------------------------------------
// K5: one warp per dst node: fused online-softmax + weighted aggregation.
//     Self loop folded into the init (m = self logit, sum = 1, acc = h[d]).
// ---------------------------------------------------------------------------
__global__ __launch_bounds__(256) void k_agg(float* __restrict__ out,
                                             const float* __restrict__ bias)
{
    int gw = (blockIdx.x * 256 + threadIdx.x) >> 5;
    int lane = threadIdx.x & 31;
    if (gw >= NN) return;
    int d = gw;

    int beg = g_start[d], cnt = g_cnt[d];
    float adst_d = g_adst[d];
    float sl = leaky(g_asrc[d] + adst_d);       // self-loop logit
    float m = sl, ssum = 1.f;
    float2 hd = ((const float2*)(g_h + (size_t)d * FOUT))[lane];
    float accx = hd.x, accy = hd.y;

    for (int base = 0; base < cnt; base += 32) {
        int n = cnt - base; if (n > 32) n = 32;
        int s = 0; float e = -1e30f;
        if (lane < n) {
            s = g_src[beg + base + lane];
            e = leaky(__ldg(&g_asrc[s]) + adst_d);
        }
        for (int j0 = 0; j0 < n; j0 += 8) {
            float2 hb[8]; float ee[8];
            #pragma unroll
            for (int jj = 0; jj < 8; jj++) {
                int ss = __shfl_sync(0xffffffffu, s, j0 + jj);
                ee[jj]  = __shfl_sync(0xffffffffu, e, j0 + jj);
                hb[jj]  = ((const float2*)(g_h + (size_t)ss * FOUT))[lane];
            }
            #pragma unroll
            for (int jj = 0; jj < 8; jj++) {
                float ev = ee[jj];
                if (ev > m) {               // uniform branch (ev broadcast)
                    float c = __expf(m - ev);
                    ssum *= c; accx *= c; accy *= c; m = ev;
                }
                float p = __expf(ev - m);   // 0 for padded lanes (ev = -1e30)
                ssum += p;
                accx += p * hb[jj].x;
                accy += p * hb[jj].y;
            }
        }
    }

    float inv = 1.f / ssum;
    float2 bv = ((const float2*)bias)[lane];
    ((float2*)(out + (size_t)d * FOUT))[lane] =
        make_float2(accx * inv + bv.x, accy * inv + bv.y);
}

// ---------------------------------------------------------------------------
extern "C" void kernel_launch(void* const* d_in, const int* in_sizes, int n_in,
                              void* d_out, int out_size)
{
    const float* x    = (const float*)d_in[0];
    const int*   ei   = (const int*)  d_in[1];   // [2, NE]: row0=src, row1=dst
    const float* W    = (const float*)d_in[2];
    const float* asrc = (const float*)d_in[3];
    const float* adst = (const float*)d_in[4];
    const float* bias = (const float*)d_in[5];
    float* out = (float*)d_out;

    k_init   <<<(NN + 255) / 256, 256>>>();
    k_count  <<<(NE + 255) / 256, 256>>>(ei);
    k_gemm   <<<(NN + GEMM_ROWS - 1) / GEMM_ROWS, 128>>>(x, W, asrc, adst);
    k_scan   <<<1, 1024>>>();
    k_scatter<<<(NE + 255) / 256, 256>>>(ei);
    k_agg    <<<(NN * 32 + 255) / 256, 256>>>(out, bias);
}

// round 4
// speedup vs baseline: 1.6263x; 1.6263x over previous
#include <cuda_runtime.h>
#include <cuda_bf16.h>

#define NN   50000
#define NE   800000
#define FIN  128
#define FOUT 64
#define SLOPE 0.2f
#define SCAN_NB ((NN + 255) / 256)   // 196

// ---------------- scratch (__device__ globals; no allocations allowed) -----
__device__ float g_h[(size_t)NN * FOUT];   // x @ W
__device__ float g_asrc[NN];               // h . att_src
__device__ float g_adst[NN];               // h . att_dst
__device__ int   g_cnt[NN];                // in-degree (excl self loop)
__device__ int   g_start[NN];              // CSR offsets
__device__ int   g_cursor[NN];             // scatter cursors
__device__ int   g_src[NE];                // CSR: src node per edge (dst-sorted)
__device__ int   g_bsum[SCAN_NB];          // per-block degree sums
__device__ int   g_boff[SCAN_NB];          // exclusive-scanned block offsets

__device__ __forceinline__ float leaky(float v) { return v > 0.f ? v : SLOPE * v; }

// packed f32x2 helpers (FFMA2 is PTX-only; ptxas never auto-fuses)
__device__ __forceinline__ long long pk2(float lo, float hi) {
    long long r;
    asm("mov.b64 %0, {%1,%2};" : "=l"(r) : "f"(lo), "f"(hi));
    return r;
}
__device__ __forceinline__ void unpk2(long long v, float& lo, float& hi) {
    asm("mov.b64 {%0,%1}, %2;" : "=f"(lo), "=f"(hi) : "l"(v));
}
__device__ __forceinline__ long long ffma2(long long a, long long b, long long c) {
    long long d;
    asm("fma.rn.f32x2 %0, %1, %2, %3;" : "=l"(d) : "l"(a), "l"(b), "l"(c));
    return d;
}

// ---------------------------------------------------------------------------
// K0: zero degree counters
// ---------------------------------------------------------------------------
__global__ __launch_bounds__(256) void k_init()
{
    int i = blockIdx.x * blockDim.x + threadIdx.x;
    if (i < NN) g_cnt[i] = 0;
}

// ---------------------------------------------------------------------------
// K1: dst histogram (RED, no return)
// ---------------------------------------------------------------------------
__global__ __launch_bounds__(256) void k_count(const int* __restrict__ ei)
{
    int i = blockIdx.x * blockDim.x + threadIdx.x;
    if (i < NE) atomicAdd(&g_cnt[ei[NE + i]], 1);
}

// ---------------------------------------------------------------------------
// K2: h = x @ W with packed f32x2 FMAs; 4 rows/warp, W+x reuse from shared.
//     Epilogue: a_src[row], a_dst[row].
// ---------------------------------------------------------------------------
#define GEMM_ROWS 16          // rows per block (4 warps x 4 rows)
__global__ __launch_bounds__(128) void k_gemm(
    const float* __restrict__ x, const float* __restrict__ W,
    const float* __restrict__ att_src, const float* __restrict__ att_dst)
{
    __shared__ long long Wsh[FIN * 32];        // 32 KB: Wsh[k*32+l]=(W[k][2l],W[k][2l+1])
    __shared__ long long Xd[GEMM_ROWS * FIN];  // 16 KB: x duplicated (v,v) per lane

    int tid = threadIdx.x;
    int row0 = blockIdx.x * GEMM_ROWS;

    const float2* W2 = (const float2*)W;
    for (int idx = tid; idx < FIN * 32; idx += 128) {
        float2 wv = W2[idx];
        Wsh[idx] = pk2(wv.x, wv.y);
    }
    for (int idx = tid; idx < GEMM_ROWS * 32; idx += 128) {
        int r = idx >> 5, c = idx & 31;
        int row = row0 + r;
        float4 v = (row < NN) ? ((const float4*)(x + (size_t)row * FIN))[c]
                              : make_float4(0.f, 0.f, 0.f, 0.f);
        long long* dst = &Xd[r * FIN + c * 4];
        dst[0] = pk2(v.x, v.x); dst[1] = pk2(v.y, v.y);
        dst[2] = pk2(v.z, v.z); dst[3] = pk2(v.w, v.w);
    }
    __syncthreads();

    int lane = tid & 31, w = tid >> 5;
    float2 as2 = ((const float2*)att_src)[lane];
    float2 ad2 = ((const float2*)att_dst)[lane];

    long long acc[4] = {0, 0, 0, 0};
    #pragma unroll 4
    for (int k = 0; k < FIN; k += 2) {
        long long w0 = Wsh[k * 32 + lane];
        long long w1 = Wsh[(k + 1) * 32 + lane];
        #pragma unroll
        for (int r = 0; r < 4; r++) {
            longlong2 xx = *(const longlong2*)&Xd[(w * 4 + r) * FIN + k];
            acc[r] = ffma2(xx.x, w0, acc[r]);
            acc[r] = ffma2(xx.y, w1, acc[r]);
        }
    }

    #pragma unroll
    for (int r = 0; r < 4; r++) {
        int row = row0 + w * 4 + r;
        if (row >= NN) continue;
        float a0, a1; unpk2(acc[r], a0, a1);
        ((float2*)(g_h + (size_t)row * FOUT))[lane] = make_float2(a0, a1);
        float ps = a0 * as2.x + a1 * as2.y;
        float pd = a0 * ad2.x + a1 * ad2.y;
        #pragma unroll
        for (int off = 16; off; off >>= 1) {
            ps += __shfl_xor_sync(0xffffffffu, ps, off);
            pd += __shfl_xor_sync(0xffffffffu, pd, off);
        }
        if (lane == 0) { g_asrc[row] = ps; g_adst[row] = pd; }
    }
}

// ---------------------------------------------------------------------------
// K3a: per-block degree sums (196 blocks)
// ---------------------------------------------------------------------------
__global__ __launch_bounds__(256) void k_scanA()
{
    __shared__ int ws[8];
    int t = threadIdx.x;
    int idx = blockIdx.x * 256 + t;
    int v = (idx < NN) ? g_cnt[idx] : 0;
    #pragma unroll
    for (int off = 16; off; off >>= 1)
        v += __shfl_xor_sync(0xffffffffu, v, off);
    if ((t & 31) == 0) ws[t >> 5] = v;
    __syncthreads();
    if (t == 0) {
        int s = 0;
        #pragma unroll
        for (int i = 0; i < 8; i++) s += ws[i];
        g_bsum[blockIdx.x] = s;
    }
}

// ---------------------------------------------------------------------------
// K3b: exclusive scan of 196 block sums (1 block)
// ---------------------------------------------------------------------------
__global__ __launch_bounds__(256) void k_scanB()
{
    __shared__ int sm[256];
    int t = threadIdx.x;
    int v = (t < SCAN_NB) ? g_bsum[t] : 0;
    sm[t] = v;
    __syncthreads();
    #pragma unroll
    for (int off = 1; off < 256; off <<= 1) {
        int u = (t >= off) ? sm[t - off] : 0;
        __syncthreads();
        sm[t] += u;
        __syncthreads();
    }
    if (t < SCAN_NB) g_boff[t] = sm[t] - v;   // exclusive
}

// ---------------------------------------------------------------------------
// K3c: per-block exclusive scan + block offset -> g_start, g_cursor
// ---------------------------------------------------------------------------
__global__ __launch_bounds__(256) void k_scanC()
{
    __shared__ int sm[256];
    int t = threadIdx.x;
    int idx = blockIdx.x * 256 + t;
    int v = (idx < NN) ? g_cnt[idx] : 0;
    sm[t] = v;
    __syncthreads();
    #pragma unroll
    for (int off = 1; off < 256; off <<= 1) {
        int u = (t >= off) ? sm[t - off] : 0;
        __syncthreads();
        sm[t] += u;
        __syncthreads();
    }
    if (idx < NN) {
        int excl = sm[t] - v + g_boff[blockIdx.x];
        g_start[idx]  = excl;
        g_cursor[idx] = excl;
    }
}

// ---------------------------------------------------------------------------
// K4: scatter edges into dst-sorted CSR (src only; logits computed in K5)
// ---------------------------------------------------------------------------
__global__ __launch_bounds__(256) void k_scatter(const int* __restrict__ ei)
{
    int i = blockIdx.x * blockDim.x + threadIdx.x;
    if (i >= NE) return;
    int d = ei[NE + i];
    int pos = atomicAdd(&g_cursor[d], 1);
    g_src[pos] = ei[i];
}

// ---------------------------------------------------------------------------
// K5: one warp per dst node: fused online-softmax + weighted aggregation.
//     Self loop folded into the init (m = self logit, sum = 1, acc = h[d]).
// ---------------------------------------------------------------------------
__global__ __launch_bounds__(256) void k_agg(float* __restrict__ out,
                                             const float* __restrict__ bias)
{
    int gw = (blockIdx.x * 256 + threadIdx.x) >> 5;
    int lane = threadIdx.x & 31;
    if (gw >= NN) return;
    int d = gw;

    int beg = g_start[d], cnt = g_cnt[d];
    float adst_d = g_adst[d];
    float sl = leaky(g_asrc[d] + adst_d);       // self-loop logit
    float m = sl, ssum = 1.f;
    float2 hd = ((const float2*)(g_h + (size_t)d * FOUT))[lane];
    float accx = hd.x, accy = hd.y;

    for (int base = 0; base < cnt; base += 32) {
        int n = cnt - base; if (n > 32) n = 32;
        int s = 0; float e = -1e30f;
        if (lane < n) {
            s = g_src[beg + base + lane];
            e = leaky(__ldg(&g_asrc[s]) + adst_d);
        }
        for (int j0 = 0; j0 < n; j0 += 8) {
            float2 hb[8]; float ee[8];
            #pragma unroll
            for (int jj = 0; jj < 8; jj++) {
                int ss = __shfl_sync(0xffffffffu, s, j0 + jj);
                ee[jj]  = __shfl_sync(0xffffffffu, e, j0 + jj);
                hb[jj]  = ((const float2*)(g_h + (size_t)ss * FOUT))[lane];
            }
            #pragma unroll
            for (int jj = 0; jj < 8; jj++) {
                float ev = ee[jj];
                if (ev > m) {               // uniform branch (ev broadcast)
                    float c = __expf(m - ev);
                    ssum *= c; accx *= c; accy *= c; m = ev;
                }
                float p = __expf(ev - m);   // 0 for padded lanes (ev = -1e30)
                ssum += p;
                accx += p * hb[jj].x;
                accy += p * hb[jj].y;
            }
        }
    }

    float inv = 1.f / ssum;
    float2 bv = ((const float2*)bias)[lane];
    ((float2*)(out + (size_t)d * FOUT))[lane] =
        make_float2(accx * inv + bv.x, accy * inv + bv.y);
}

// ---------------------------------------------------------------------------
extern "C" void kernel_launch(void* const* d_in, const int* in_sizes, int n_in,
                              void* d_out, int out_size)
{
    const float* x    = (const float*)d_in[0];
    const int*   ei   = (const int*)  d_in[1];   // [2, NE]: row0=src, row1=dst
    const float* W    = (const float*)d_in[2];
    const float* asrc = (const float*)d_in[3];
    const float* adst = (const float*)d_in[4];
    const float* bias = (const float*)d_in[5];
    float* out = (float*)d_out;

    k_init   <<<(NN + 255) / 256, 256>>>();
    k_count  <<<(NE + 255) / 256, 256>>>(ei);
    k_gemm   <<<(NN + GEMM_ROWS - 1) / GEMM_ROWS, 128>>>(x, W, asrc, adst);
    k_scanA  <<<SCAN_NB, 256>>>();
    k_scanB  <<<1, 256>>>();
    k_scanC  <<<SCAN_NB, 256>>>();
    k_scatter<<<(NE + 255) / 256, 256>>>(ei);
    k_agg    <<<(NN * 32 + 255) / 256, 256>>>(out, bias);
}

// round 5
// speedup vs baseline: 1.8269x; 1.1233x over previous
#include <cuda_runtime.h>
#include <cuda_bf16.h>

#define NN   50000
#define NE   800000
#define FIN  128
#define FOUT 64
#define SLOPE 0.2f
#define SCAN_NB ((NN + 255) / 256)   // 196

// ---------------- scratch (__device__ globals; no allocations allowed) -----
__device__ float g_h[(size_t)NN * FOUT];   // x @ W
__device__ float g_asrc[NN];               // h . att_src
__device__ float g_adst[NN];               // h . att_dst
__device__ int   g_cnt[NN];                // in-degree (zeroed by k_agg each run)
__device__ int   g_start[NN];              // CSR offsets
__device__ int   g_cursor[NN];             // scatter cursors
__device__ int   g_src[NE];                // CSR: src node per edge (dst-sorted)
__device__ int   g_bsum[SCAN_NB];          // per-block degree sums
__device__ int   g_boff[SCAN_NB];          // exclusive-scanned block offsets

__device__ __forceinline__ float leaky(float v) { return v > 0.f ? v : SLOPE * v; }

// packed f32x2 helpers (FFMA2 is PTX-only; ptxas never auto-fuses)
__device__ __forceinline__ long long pk2(float lo, float hi) {
    long long r;
    asm("mov.b64 %0, {%1,%2};" : "=l"(r) : "f"(lo), "f"(hi));
    return r;
}
__device__ __forceinline__ void unpk2(long long v, float& lo, float& hi) {
    asm("mov.b64 {%0,%1}, %2;" : "=f"(lo), "=f"(hi) : "l"(v));
}
__device__ __forceinline__ long long ffma2(long long a, long long b, long long c) {
    long long d;
    asm("fma.rn.f32x2 %0, %1, %2, %3;" : "=l"(d) : "l"(a), "l"(b), "l"(c));
    return d;
}

// ---------------------------------------------------------------------------
// K1: dst histogram (g_cnt arrives zeroed: static init / zeroed by prev k_agg)
// ---------------------------------------------------------------------------
__global__ __launch_bounds__(256) void k_count(const int* __restrict__ ei)
{
    int i = blockIdx.x * blockDim.x + threadIdx.x;
    if (i < NE) atomicAdd(&g_cnt[ei[NE + i]], 1);
}

// ---------------------------------------------------------------------------
// K2: h = x @ W with packed f32x2 FMAs; 4 rows/warp, W+x reuse from shared.
//     Epilogue: a_src[row], a_dst[row].
// ---------------------------------------------------------------------------
#define GEMM_ROWS 16          // rows per block (4 warps x 4 rows)
__global__ __launch_bounds__(128) void k_gemm(
    const float* __restrict__ x, const float* __restrict__ W,
    const float* __restrict__ att_src, const float* __restrict__ att_dst)
{
    __shared__ long long Wsh[FIN * 32];        // 32 KB
    __shared__ long long Xd[GEMM_ROWS * FIN];  // 16 KB: x duplicated (v,v)

    int tid = threadIdx.x;
    int row0 = blockIdx.x * GEMM_ROWS;

    const float2* W2 = (const float2*)W;
    for (int idx = tid; idx < FIN * 32; idx += 128) {
        float2 wv = W2[idx];
        Wsh[idx] = pk2(wv.x, wv.y);
    }
    for (int idx = tid; idx < GEMM_ROWS * 32; idx += 128) {
        int r = idx >> 5, c = idx & 31;
        int row = row0 + r;
        float4 v = (row < NN) ? ((const float4*)(x + (size_t)row * FIN))[c]
                              : make_float4(0.f, 0.f, 0.f, 0.f);
        long long* dst = &Xd[r * FIN + c * 4];
        dst[0] = pk2(v.x, v.x); dst[1] = pk2(v.y, v.y);
        dst[2] = pk2(v.z, v.z); dst[3] = pk2(v.w, v.w);
    }
    __syncthreads();

    int lane = tid & 31, w = tid >> 5;
    float2 as2 = ((const float2*)att_src)[lane];
    float2 ad2 = ((const float2*)att_dst)[lane];

    long long acc[4] = {0, 0, 0, 0};
    #pragma unroll 4
    for (int k = 0; k < FIN; k += 2) {
        long long w0 = Wsh[k * 32 + lane];
        long long w1 = Wsh[(k + 1) * 32 + lane];
        #pragma unroll
        for (int r = 0; r < 4; r++) {
            longlong2 xx = *(const longlong2*)&Xd[(w * 4 + r) * FIN + k];
            acc[r] = ffma2(xx.x, w0, acc[r]);
            acc[r] = ffma2(xx.y, w1, acc[r]);
        }
    }

    #pragma unroll
    for (int r = 0; r < 4; r++) {
        int row = row0 + w * 4 + r;
        if (row >= NN) continue;
        float a0, a1; unpk2(acc[r], a0, a1);
        ((float2*)(g_h + (size_t)row * FOUT))[lane] = make_float2(a0, a1);
        float ps = a0 * as2.x + a1 * as2.y;
        float pd = a0 * ad2.x + a1 * ad2.y;
        #pragma unroll
        for (int off = 16; off; off >>= 1) {
            ps += __shfl_xor_sync(0xffffffffu, ps, off);
            pd += __shfl_xor_sync(0xffffffffu, pd, off);
        }
        if (lane == 0) { g_asrc[row] = ps; g_adst[row] = pd; }
    }
}

// ---------------------------------------------------------------------------
// K3a/b/c: hierarchical exclusive scan of degrees
// ---------------------------------------------------------------------------
__global__ __launch_bounds__(256) void k_scanA()
{
    __shared__ int ws[8];
    int t = threadIdx.x;
    int idx = blockIdx.x * 256 + t;
    int v = (idx < NN) ? g_cnt[idx] : 0;
    #pragma unroll
    for (int off = 16; off; off >>= 1)
        v += __shfl_xor_sync(0xffffffffu, v, off);
    if ((t & 31) == 0) ws[t >> 5] = v;
    __syncthreads();
    if (t == 0) {
        int s = 0;
        #pragma unroll
        for (int i = 0; i < 8; i++) s += ws[i];
        g_bsum[blockIdx.x] = s;
    }
}

__global__ __launch_bounds__(256) void k_scanB()
{
    __shared__ int sm[256];
    int t = threadIdx.x;
    int v = (t < SCAN_NB) ? g_bsum[t] : 0;
    sm[t] = v;
    __syncthreads();
    #pragma unroll
    for (int off = 1; off < 256; off <<= 1) {
        int u = (t >= off) ? sm[t - off] : 0;
        __syncthreads();
        sm[t] += u;
        __syncthreads();
    }
    if (t < SCAN_NB) g_boff[t] = sm[t] - v;   // exclusive
}

__global__ __launch_bounds__(256) void k_scanC()
{
    __shared__ int sm[256];
    int t = threadIdx.x;
    int idx = blockIdx.x * 256 + t;
    int v = (idx < NN) ? g_cnt[idx] : 0;
    sm[t] = v;
    __syncthreads();
    #pragma unroll
    for (int off = 1; off < 256; off <<= 1) {
        int u = (t >= off) ? sm[t - off] : 0;
        __syncthreads();
        sm[t] += u;
        __syncthreads();
    }
    if (idx < NN) {
        int excl = sm[t] - v + g_boff[blockIdx.x];
        g_start[idx]  = excl;
        g_cursor[idx] = excl;
    }
}

// ---------------------------------------------------------------------------
// K4: scatter edges into dst-sorted CSR
// ---------------------------------------------------------------------------
__global__ __launch_bounds__(256) void k_scatter(const int* __restrict__ ei)
{
    int i = blockIdx.x * blockDim.x + threadIdx.x;
    if (i >= NE) return;
    int d = ei[NE + i];
    int pos = atomicAdd(&g_cursor[d], 1);
    g_src[pos] = ei[i];
}

// ---------------------------------------------------------------------------
// K5: one warp per dst node; TWO independent half-warp edge streams, each
//     doing online-softmax with float4/lane gathers; merged at the end.
//     Self loop folded into half 0's init. Also zeroes g_cnt for next run.
// ---------------------------------------------------------------------------
__global__ __launch_bounds__(256) void k_agg(float* __restrict__ out,
                                             const float* __restrict__ bias)
{
    int gw = (blockIdx.x * 256 + threadIdx.x) >> 5;
    int lane = threadIdx.x & 31;
    if (gw >= NN) return;
    int d = gw;
    int eh = lane >> 4, f = lane & 15;

    int beg = g_start[d];
    int cnt = g_cnt[d];
    float adst_d = g_adst[d];
    float sl = leaky(g_asrc[d] + adst_d);        // self-loop logit

    float m, ssum;
    float4 acc;
    if (eh == 0) {
        m = sl; ssum = 1.f;
        acc = ((const float4*)(g_h + (size_t)d * FOUT))[f];
    } else {
        m = -1e30f; ssum = 0.f;
        acc = make_float4(0.f, 0.f, 0.f, 0.f);
    }

    for (int base = 0; base < cnt; base += 32) {
        int n = cnt - base; if (n > 32) n = 32;
        int s = 0; float e = -1e30f;
        if (lane < n) {
            s = g_src[beg + base + lane];
            e = leaky(__ldg(&g_asrc[s]) + adst_d);
        }
        for (int j0 = 0; j0 < n; j0 += 8) {       // 8 edges: 4 per half
            float4 hb[4]; float ee[4];
            #pragma unroll
            for (int u = 0; u < 4; u++) {
                int j = j0 + 2 * u + eh;
                int ss = __shfl_sync(0xffffffffu, s, j);
                ee[u]  = __shfl_sync(0xffffffffu, e, j);
                hb[u]  = ((const float4*)(g_h + (size_t)ss * FOUT))[f];
            }
            #pragma unroll
            for (int u = 0; u < 4; u++) {
                float ev = ee[u];                 // uniform within half-warp
                if (ev > m) {
                    float c = __expf(m - ev);
                    ssum *= c;
                    acc.x *= c; acc.y *= c; acc.z *= c; acc.w *= c;
                    m = ev;
                }
                float p = __expf(ev - m);         // 0 for padded edges
                ssum += p;
                acc.x += p * hb[u].x; acc.y += p * hb[u].y;
                acc.z += p * hb[u].z; acc.w += p * hb[u].w;
            }
        }
    }

    // merge the two half-warp softmax states
    float mo = __shfl_xor_sync(0xffffffffu, m, 16);
    float so = __shfl_xor_sync(0xffffffffu, ssum, 16);
    float4 ao;
    ao.x = __shfl_xor_sync(0xffffffffu, acc.x, 16);
    ao.y = __shfl_xor_sync(0xffffffffu, acc.y, 16);
    ao.z = __shfl_xor_sync(0xffffffffu, acc.z, 16);
    ao.w = __shfl_xor_sync(0xffffffffu, acc.w, 16);
    float M  = fmaxf(m, mo);
    float c0 = __expf(m - M), c1 = __expf(mo - M);
    float inv = 1.f / (ssum * c0 + so * c1);

    if (eh == 0) {
        float4 bv = ((const float4*)bias)[f];
        float4 r;
        r.x = (acc.x * c0 + ao.x * c1) * inv + bv.x;
        r.y = (acc.y * c0 + ao.y * c1) * inv + bv.y;
        r.z = (acc.z * c0 + ao.z * c1) * inv + bv.z;
        r.w = (acc.w * c0 + ao.w * c1) * inv + bv.w;
        ((float4*)(out + (size_t)d * FOUT))[f] = r;
    }
    if (lane == 0) g_cnt[d] = 0;                  // ready for next run
}

// ---------------------------------------------------------------------------
extern "C" void kernel_launch(void* const* d_in, const int* in_sizes, int n_in,
                              void* d_out, int out_size)
{
    const float* x    = (const float*)d_in[0];
    const int*   ei   = (const int*)  d_in[1];   // [2, NE]: row0=src, row1=dst
    const float* W    = (const float*)d_in[2];
    const float* asrc = (const float*)d_in[3];
    const float* adst = (const float*)d_in[4];
    const float* bias = (const float*)d_in[5];
    float* out = (float*)d_out;

    // one-time host-side resources (created outside capture on first call)
    static cudaStream_t s1 = nullptr;
    static cudaEvent_t ev_fork = nullptr, ev_join = nullptr;
    if (s1 == nullptr) {
        cudaStreamCreateWithFlags(&s1, cudaStreamNonBlocking);
        cudaEventCreateWithFlags(&ev_fork, cudaEventDisableTiming);
        cudaEventCreateWithFlags(&ev_join, cudaEventDisableTiming);
    }

    // fork: GEMM (x,W only) runs on s1 concurrently with CSR build (ei only)
    cudaEventRecord(ev_fork, 0);
    cudaStreamWaitEvent(s1, ev_fork, 0);
    k_gemm<<<(NN + GEMM_ROWS - 1) / GEMM_ROWS, 128, 0, s1>>>(x, W, asrc, adst);
    cudaEventRecord(ev_join, s1);

    k_count  <<<(NE + 255) / 256, 256>>>(ei);
    k_scanA  <<<SCAN_NB, 256>>>();
    k_scanB  <<<1, 256>>>();
    k_scanC  <<<SCAN_NB, 256>>>();
    k_scatter<<<(NE + 255) / 256, 256>>>(ei);

    cudaStreamWaitEvent(0, ev_join, 0);          // join before aggregation
    k_agg<<<(NN * 32 + 255) / 256, 256>>>(out, bias);
}